// round 6
// baseline (speedup 1.0000x reference)
#include <cuda_runtime.h>
#include <cuda_fp16.h>

// Swin window attention, fully fused: one CTA per 8x8 window, 4 CTAs/SM.
// Q never touches smem; half2 softmax via ex2.approx.f16x2 (log2-domain);
// rel-pos bias injected as MMA C-operand; residual kept in smem (no x re-read).

#define NWIN   8192
#define TPB    256
#define LOG2E  1.4426950408889634f

// smem layout (bytes)
#define OFF_XF   0        // float [64][68] 17408  (raw x, residual)
#define OFF_XN   17408    // half  [64][72]  9216  (LN output Z; later attn-out AO)
#define OFF_KV   26624    // half  [64][136] 17408 (K cols 0-63, V cols 64-127)
#define SMEM_BYTES 44032

// pre-baked tables (prep kernel fills these)
__device__ unsigned g_qkvfrag[3072 * 2];   // [ntile0..23][kt0..3][lane][2]  (LN+scale folded)
__device__ unsigned g_projfrag[1024 * 2];  // [ntile0..7][kt][lane][2]
__device__ unsigned g_qkvbh[96];           // half2 qkv bias per col-pair (scale folded)
__device__ unsigned g_biasfh[4096 * 2];    // [warp][mt][j][lane][2] bias*log2e half2 frags

__device__ __forceinline__ unsigned packh2f(float lo, float hi) {
    __half2 h = __floats2half2_rn(lo, hi);
    return *reinterpret_cast<unsigned*>(&h);
}

__global__ void prep_kernel(const float* __restrict__ qw, const float* __restrict__ pw,
                            const float* __restrict__ nw, const float* __restrict__ nb,
                            const float* __restrict__ rpb) {
    int idx = blockIdx.x * blockDim.x + threadIdx.x;   // 32 blocks * 256 = 8192

    if (idx < 3072) {  // qkv weight fragments (norm_w + q-scale*log2e folded)
        int lane = idx & 31, kt = (idx >> 5) & 3, ntile = idx >> 7;
        int n  = ntile * 8 + (lane >> 2);
        int k0 = kt * 16 + (lane & 3) * 2;
        float sc = (n < 64) ? 0.25f * LOG2E : 1.0f;
        const float* wr = qw + n * 64;
        g_qkvfrag[idx * 2 + 0] = packh2f(wr[k0] * nw[k0] * sc,         wr[k0 + 1] * nw[k0 + 1] * sc);
        g_qkvfrag[idx * 2 + 1] = packh2f(wr[k0 + 8] * nw[k0 + 8] * sc, wr[k0 + 9] * nw[k0 + 9] * sc);
    }
    if (idx < 1024) {  // proj weight fragments
        int lane = idx & 31, kt = (idx >> 5) & 3, ntile = idx >> 7;
        int n  = ntile * 8 + (lane >> 2);
        int k0 = kt * 16 + (lane & 3) * 2;
        const float* wr = pw + n * 64;
        g_projfrag[idx * 2 + 0] = packh2f(wr[k0],     wr[k0 + 1]);
        g_projfrag[idx * 2 + 1] = packh2f(wr[k0 + 8], wr[k0 + 9]);
    }
    if (idx < 96) {    // folded LN-bias through qkv (per output col pair), scale folded
        float b0 = 0.f, b1 = 0.f;
        int c = idx * 2;
        for (int k = 0; k < 64; k++) {
            b0 += nb[k] * qw[c * 64 + k];
            b1 += nb[k] * qw[(c + 1) * 64 + k];
        }
        float sc = (c < 64) ? 0.25f * LOG2E : 1.0f;
        g_qkvbh[idx] = packh2f(b0 * sc, b1 * sc);
    }
    if (idx < 4096) {  // rel-pos bias fragments (half2, *log2e), layout [warp][mt][j][lane][2]
        int lane = idx & 31, j = (idx >> 5) & 7, mt = (idx >> 8) & 1, warp = idx >> 9;
        int h  = warp >> 1;
        int m0 = (warp & 1) * 32;
        int g  = lane >> 2, tig = lane & 3;
        int rr = m0 + mt * 16 + g;
        int cc = j * 8 + tig * 2;
        auto bias = [&](int r, int c) {
            int dy = (r >> 3) - (c >> 3);
            int dx = (r & 7) - (c & 7);
            return rpb[((dy + 7) * 15 + (dx + 7)) * 4 + h] * LOG2E;
        };
        g_biasfh[idx * 2 + 0] = packh2f(bias(rr, cc),     bias(rr, cc + 1));
        g_biasfh[idx * 2 + 1] = packh2f(bias(rr + 8, cc), bias(rr + 8, cc + 1));
    }
}

__device__ __forceinline__ unsigned saddr(const void* p) {
    return (unsigned)__cvta_generic_to_shared(p);
}
__device__ __forceinline__ void ldsm_x4(unsigned a, unsigned& r0, unsigned& r1, unsigned& r2, unsigned& r3) {
    asm volatile("ldmatrix.sync.aligned.m8n8.x4.shared.b16 {%0,%1,%2,%3}, [%4];"
                 : "=r"(r0), "=r"(r1), "=r"(r2), "=r"(r3) : "r"(a));
}
__device__ __forceinline__ void ldsm_x4t(unsigned a, unsigned& r0, unsigned& r1, unsigned& r2, unsigned& r3) {
    asm volatile("ldmatrix.sync.aligned.m8n8.x4.trans.shared.b16 {%0,%1,%2,%3}, [%4];"
                 : "=r"(r0), "=r"(r1), "=r"(r2), "=r"(r3) : "r"(a));
}
__device__ __forceinline__ void mmah(uint2& c, unsigned a0, unsigned a1, unsigned a2, unsigned a3,
                                     unsigned b0, unsigned b1) {
    asm volatile("mma.sync.aligned.m16n8k16.row.col.f16.f16.f16.f16 "
                 "{%0,%1}, {%2,%3,%4,%5}, {%6,%7}, {%0,%1};"
                 : "+r"(c.x), "+r"(c.y)
                 : "r"(a0), "r"(a1), "r"(a2), "r"(a3), "r"(b0), "r"(b1));
}
__device__ __forceinline__ unsigned hadd2u(unsigned a, unsigned b) {
    __half2 r = __hadd2(*(__half2*)&a, *(__half2*)&b);
    return *(unsigned*)&r;
}
__device__ __forceinline__ unsigned hsub2u(unsigned a, unsigned b) {
    __half2 r = __hsub2(*(__half2*)&a, *(__half2*)&b);
    return *(unsigned*)&r;
}
__device__ __forceinline__ unsigned hmax2u(unsigned a, unsigned b) {
    __half2 r = __hmax2(*(__half2*)&a, *(__half2*)&b);
    return *(unsigned*)&r;
}
__device__ __forceinline__ unsigned hmul2u(unsigned a, unsigned b) {
    __half2 r = __hmul2(*(__half2*)&a, *(__half2*)&b);
    return *(unsigned*)&r;
}
__device__ __forceinline__ unsigned ex2h2(unsigned a) {
    unsigned r;
    asm("ex2.approx.f16x2 %0, %1;" : "=r"(r) : "r"(a));
    return r;
}
__device__ __forceinline__ unsigned hswap(unsigned a) {      // swap the two halves
    return __byte_perm(a, a, 0x1032);
}
__device__ __forceinline__ float2 h2f2(unsigned u) {
    return __half22float2(*(__half2*)&u);
}
__device__ __forceinline__ float hlo2f(unsigned u) {
    return __half2float(__low2half(*(__half2*)&u));
}

__global__ __launch_bounds__(256, 4)
void ewa_kernel(const float* __restrict__ x,
                const float* __restrict__ ascale,
                float* __restrict__ out) {
    extern __shared__ char smem[];
    float*  Xf = (float*)(smem + OFF_XF);    // [64][68]
    __half* XN = (__half*)(smem + OFF_XN);   // [64][72]  Z / AO
    __half* KV = (__half*)(smem + OFF_KV);   // [64][136] K | V

    const int tid  = threadIdx.x;
    const int lane = tid & 31;
    const int warp = tid >> 5;
    const int g    = lane >> 2;
    const int tig  = lane & 3;
    const int l2   = lane & 15;

    const int win = blockIdx.x;
    const int b   = win >> 10;
    const int rem = win & 1023;
    const int wy  = rem >> 5;
    const int wx  = rem & 31;

    const int h  = warp >> 1;          // head (phases 2-3)
    const int m0 = (warp & 1) * 32;

    // ---- Phase 1: token-major load + in-register LayerNorm; keep raw x in Xf ----
    {
        int t = tid >> 2, q = tid & 3;            // token, channel quarter
        int pix = (wy * 8 + (t >> 3)) * 256 + wx * 8 + (t & 7);
        const float* base = x + (b * 64 + q * 16) * 65536 + pix;
        float v[16];
        #pragma unroll
        for (int i = 0; i < 16; i++) v[i] = base[i * 65536];
        float* xdst = Xf + t * 68 + q * 16;
        #pragma unroll
        for (int k = 0; k < 4; k++)
            *(float4*)(xdst + k * 4) = make_float4(v[4 * k], v[4 * k + 1], v[4 * k + 2], v[4 * k + 3]);
        float s = 0.f, ss = 0.f;
        #pragma unroll
        for (int i = 0; i < 16; i++) { s += v[i]; ss += v[i] * v[i]; }
        s  += __shfl_xor_sync(0xffffffffu, s, 1);  ss += __shfl_xor_sync(0xffffffffu, ss, 1);
        s  += __shfl_xor_sync(0xffffffffu, s, 2);  ss += __shfl_xor_sync(0xffffffffu, ss, 2);
        float mu   = s * (1.f / 64.f);
        float var  = ss * (1.f / 64.f) - mu * mu;
        float rstd = rsqrtf(var + 1e-5f);
        unsigned h8[8];
        #pragma unroll
        for (int i = 0; i < 8; i++)
            h8[i] = packh2f((v[2 * i] - mu) * rstd, (v[2 * i + 1] - mu) * rstd);
        uint4* dst = (uint4*)(XN + t * 72 + q * 16);
        dst[0] = make_uint4(h8[0], h8[1], h8[2], h8[3]);
        dst[1] = make_uint4(h8[4], h8[5], h8[6], h8[7]);
    }
    __syncthreads();

    // ---- Phase 2: QKV GEMM. Q for own (head, rows) stays in registers; K/V -> smem ----
    unsigned qa[2][4];   // Q as A-fragments for QK^T, per mt
    {
        uint2 qacc[2][2], kvacc[2][4];
        #pragma unroll
        for (int mt = 0; mt < 2; mt++) {
            qacc[mt][0] = make_uint2(0u, 0u); qacc[mt][1] = make_uint2(0u, 0u);
            #pragma unroll
            for (int j = 0; j < 4; j++) kvacc[mt][j] = make_uint2(0u, 0u);
        }
        #pragma unroll
        for (int kt = 0; kt < 4; kt++) {
            unsigned a[2][4];
            #pragma unroll
            for (int mt = 0; mt < 2; mt++)
                ldsm_x4(saddr(XN + (m0 + mt * 16 + l2) * 72 + kt * 16 + (lane >> 4) * 8),
                        a[mt][0], a[mt][1], a[mt][2], a[mt][3]);
            uint2 qb[2], kvb[4];
            #pragma unroll
            for (int j = 0; j < 2; j++)
                qb[j] = *(const uint2*)(g_qkvfrag + (((h * 2 + j) * 4 + kt) * 32 + lane) * 2);
            #pragma unroll
            for (int j = 0; j < 4; j++)
                kvb[j] = *(const uint2*)(g_qkvfrag + (((8 + h * 4 + j) * 4 + kt) * 32 + lane) * 2);
            #pragma unroll
            for (int mt = 0; mt < 2; mt++) {
                #pragma unroll
                for (int j = 0; j < 2; j++)
                    mmah(qacc[mt][j], a[mt][0], a[mt][1], a[mt][2], a[mt][3], qb[j].x, qb[j].y);
                #pragma unroll
                for (int j = 0; j < 4; j++)
                    mmah(kvacc[mt][j], a[mt][0], a[mt][1], a[mt][2], a[mt][3], kvb[j].x, kvb[j].y);
            }
        }
        // Q: D-frag (+bias) == A-frag for QK^T
        unsigned bq0 = g_qkvbh[h * 8 + tig];
        unsigned bq1 = g_qkvbh[h * 8 + 4 + tig];
        #pragma unroll
        for (int mt = 0; mt < 2; mt++) {
            qa[mt][0] = hadd2u(qacc[mt][0].x, bq0);
            qa[mt][1] = hadd2u(qacc[mt][0].y, bq0);
            qa[mt][2] = hadd2u(qacc[mt][1].x, bq1);
            qa[mt][3] = hadd2u(qacc[mt][1].y, bq1);
        }
        // K/V -> smem (smem col = global col - 64)
        #pragma unroll
        for (int j = 0; j < 4; j++) {
            int col = h * 32 + j * 8 + tig * 2;
            unsigned bh = g_qkvbh[32 + h * 16 + j * 4 + tig];
            #pragma unroll
            for (int mt = 0; mt < 2; mt++) {
                int row = m0 + mt * 16 + g;
                *(unsigned*)(KV + row * 136 + col)       = hadd2u(kvacc[mt][j].x, bh);
                *(unsigned*)(KV + (row + 8) * 136 + col) = hadd2u(kvacc[mt][j].y, bh);
            }
        }
    }
    __syncthreads();

    // ---- Phase 3: attention (log2-domain logits, half2 softmax, bias as C-init) ----
    {
        unsigned kb[8][2];
        #pragma unroll
        for (int jp = 0; jp < 4; jp++) {        // K fragments via ldmatrix.x4 (2 n-tiles each)
            unsigned r0, r1, r2, r3;
            int j  = (lane >> 4);               // n-tile within pair (lane groups 0-1 / 2-3)
            int kh = (lane >> 3) & 1;
            ldsm_x4(saddr(KV + ((jp * 2 + j) * 8 + (lane & 7)) * 136 + h * 16 + kh * 8),
                    r0, r1, r2, r3);
            kb[jp * 2 + 0][0] = r0; kb[jp * 2 + 0][1] = r1;
            kb[jp * 2 + 1][0] = r2; kb[jp * 2 + 1][1] = r3;
        }

        #pragma unroll
        for (int mt = 0; mt < 2; mt++) {
            const uint2* bfh = (const uint2*)(g_biasfh) + ((warp * 2 + mt) * 8) * 32 + lane;
            uint2 s[8];
            #pragma unroll
            for (int j = 0; j < 8; j++) {
                uint2 bv = bfh[j * 32];
                s[j].x = bv.x; s[j].y = bv.y;    // bias as accumulator init
                mmah(s[j], qa[mt][0], qa[mt][1], qa[mt][2], qa[mt][3], kb[j][0], kb[j][1]);
            }

            unsigned mh0 = packh2f(-65504.f, -65504.f), mh1 = mh0;
            #pragma unroll
            for (int j = 0; j < 8; j++) {
                mh0 = hmax2u(mh0, s[j].x);
                mh1 = hmax2u(mh1, s[j].y);
            }
            mh0 = hmax2u(mh0, __shfl_xor_sync(0xffffffffu, mh0, 1));
            mh0 = hmax2u(mh0, __shfl_xor_sync(0xffffffffu, mh0, 2));
            mh0 = hmax2u(mh0, hswap(mh0));            // row max in both halves
            mh1 = hmax2u(mh1, __shfl_xor_sync(0xffffffffu, mh1, 1));
            mh1 = hmax2u(mh1, __shfl_xor_sync(0xffffffffu, mh1, 2));
            mh1 = hmax2u(mh1, hswap(mh1));

            unsigned sum0 = 0u, sum1 = 0u;            // half2 zeros
            #pragma unroll
            for (int j = 0; j < 8; j++) {
                s[j].x = ex2h2(hsub2u(s[j].x, mh0));  // p = 2^(l - m)
                s[j].y = ex2h2(hsub2u(s[j].y, mh1));
                sum0 = hadd2u(sum0, s[j].x);
                sum1 = hadd2u(sum1, s[j].y);
            }
            sum0 = hadd2u(sum0, __shfl_xor_sync(0xffffffffu, sum0, 1));
            sum0 = hadd2u(sum0, __shfl_xor_sync(0xffffffffu, sum0, 2));
            sum0 = hadd2u(sum0, hswap(sum0));
            sum1 = hadd2u(sum1, __shfl_xor_sync(0xffffffffu, sum1, 1));
            sum1 = hadd2u(sum1, __shfl_xor_sync(0xffffffffu, sum1, 2));
            sum1 = hadd2u(sum1, hswap(sum1));

            // AV with unnormalized probs; V fragments via ldmatrix.x4.trans
            uint2 o[2];
            o[0].x = o[0].y = o[1].x = o[1].y = 0u;
            #pragma unroll
            for (int kt = 0; kt < 4; kt++) {
                unsigned v0, v1, v2, v3;
                ldsm_x4t(saddr(KV + (kt * 16 + (lane & 7) + ((lane >> 3) & 1) * 8) * 136
                               + 64 + h * 16 + (lane >> 4) * 8),
                         v0, v1, v2, v3);
                mmah(o[0], s[2 * kt].x, s[2 * kt].y, s[2 * kt + 1].x, s[2 * kt + 1].y, v0, v1);
                mmah(o[1], s[2 * kt].x, s[2 * kt].y, s[2 * kt + 1].x, s[2 * kt + 1].y, v2, v3);
            }
            float f0 = 1.f / hlo2f(sum0);
            float f1 = 1.f / hlo2f(sum1);
            unsigned i0 = packh2f(f0, f0);
            unsigned i1 = packh2f(f1, f1);
            #pragma unroll
            for (int nt = 0; nt < 2; nt++) {
                int row = m0 + mt * 16 + g;
                int col = h * 16 + nt * 8 + tig * 2;
                *(unsigned*)(XN + row * 72 + col)       = hmul2u(o[nt].x, i0);
                *(unsigned*)(XN + (row + 8) * 72 + col) = hmul2u(o[nt].y, i1);
            }
        }
    }
    __syncthreads();

    // ---- Phase 4: proj GEMM [64,64]x[64,64] + residual (from smem) + write out ----
    {
        const int ntb = (warp >> 1) * 2;      // ntile base (8-col tiles)
        uint2 acc[2][2];
        acc[0][0] = make_uint2(0u, 0u); acc[0][1] = make_uint2(0u, 0u);
        acc[1][0] = make_uint2(0u, 0u); acc[1][1] = make_uint2(0u, 0u);
        #pragma unroll
        for (int kt = 0; kt < 4; kt++) {
            unsigned a[2][4];
            #pragma unroll
            for (int mt = 0; mt < 2; mt++)
                ldsm_x4(saddr(XN + (m0 + mt * 16 + l2) * 72 + kt * 16 + (lane >> 4) * 8),
                        a[mt][0], a[mt][1], a[mt][2], a[mt][3]);
            uint2 bf[2];
            #pragma unroll
            for (int nt = 0; nt < 2; nt++)
                bf[nt] = *(const uint2*)(g_projfrag + (((ntb + nt) * 4 + kt) * 32 + lane) * 2);
            #pragma unroll
            for (int mt = 0; mt < 2; mt++)
                #pragma unroll
                for (int nt = 0; nt < 2; nt++)
                    mmah(acc[mt][nt], a[mt][0], a[mt][1], a[mt][2], a[mt][3], bf[nt].x, bf[nt].y);
        }
        float ssc = ascale[0];
        #pragma unroll
        for (int mt = 0; mt < 2; mt++)
            #pragma unroll
            for (int nt = 0; nt < 2; nt++) {
                int ch = (ntb + nt) * 8 + tig * 2;
                float2 lo = h2f2(acc[mt][nt].x);   // rows m0+mt*16+g
                float2 hi = h2f2(acc[mt][nt].y);   // rows +8
                #pragma unroll
                for (int hf = 0; hf < 2; hf++) {
                    int row = m0 + mt * 16 + g + hf * 8;
                    float2 v = hf ? hi : lo;
                    float2 xr = *(const float2*)(Xf + row * 68 + ch);
                    int gi0 = ((b * 64 + ch) * 256 + wy * 8 + (row >> 3)) * 256 + wx * 8 + (row & 7);
                    out[gi0]         = xr.x + ssc * v.x;
                    out[gi0 + 65536] = xr.y + ssc * v.y;   // ch+1
                }
            }
    }
}

extern "C" void kernel_launch(void* const* d_in, const int* in_sizes, int n_in,
                              void* d_out, int out_size) {
    const float* x  = (const float*)d_in[0];
    const float* nw = (const float*)d_in[1];
    const float* nb = (const float*)d_in[2];
    const float* qw = (const float*)d_in[3];
    const float* pw = (const float*)d_in[4];
    const float* sc = (const float*)d_in[5];
    const float* rp = (const float*)d_in[6];
    float* out = (float*)d_out;

    cudaFuncSetAttribute(ewa_kernel, cudaFuncAttributeMaxDynamicSharedMemorySize, SMEM_BYTES);

    prep_kernel<<<32, 256>>>(qw, pw, nw, nb, rp);
    ewa_kernel<<<NWIN, TPB, SMEM_BYTES>>>(x, sc, out);
}

// round 7
// speedup vs baseline: 1.0432x; 1.0432x over previous
#include <cuda_runtime.h>
#include <cuda_fp16.h>

// Swin window attention, fully fused: one CTA per 8x8 window, 4 CTAs/SM.
// Q never touches smem; half2 softmax via ex2.approx.f16x2 (log2-domain);
// rel-pos bias injected as MMA C-operand; K/V fragments via ldmatrix.x4.
// 26.6 KB smem so CTA-invariant fragment tables stay L1-resident.

#define NWIN   8192
#define TPB    256
#define LOG2E  1.4426950408889634f

// smem layout (bytes)
#define OFF_XN   0        // half [64][72]   9216  (LN output Z; later attn-out AO)
#define OFF_KV   9216     // half [64][136] 17408  (K cols 0-63, V cols 64-127)
#define SMEM_BYTES 26624

// pre-baked tables (prep kernel fills these)
__device__ unsigned g_qkvfrag[3072 * 2];   // [ntile0..23][kt0..3][lane][2]  (LN+scale folded)
__device__ unsigned g_projfrag[1024 * 2];  // [ntile0..7][kt][lane][2]
__device__ unsigned g_qkvbh[96];           // half2 qkv bias per col-pair (scale folded)
__device__ unsigned g_biasfh[4096 * 2];    // [warp][mt][j][lane][2] bias*log2e half2 frags

__device__ __forceinline__ unsigned packh2f(float lo, float hi) {
    __half2 h = __floats2half2_rn(lo, hi);
    return *reinterpret_cast<unsigned*>(&h);
}

__global__ void prep_kernel(const float* __restrict__ qw, const float* __restrict__ pw,
                            const float* __restrict__ nw, const float* __restrict__ nb,
                            const float* __restrict__ rpb) {
    int idx = blockIdx.x * blockDim.x + threadIdx.x;   // 32 blocks * 256 = 8192

    if (idx < 3072) {  // qkv weight fragments (norm_w + q-scale*log2e folded)
        int lane = idx & 31, kt = (idx >> 5) & 3, ntile = idx >> 7;
        int n  = ntile * 8 + (lane >> 2);
        int k0 = kt * 16 + (lane & 3) * 2;
        float sc = (n < 64) ? 0.25f * LOG2E : 1.0f;
        const float* wr = qw + n * 64;
        g_qkvfrag[idx * 2 + 0] = packh2f(wr[k0] * nw[k0] * sc,         wr[k0 + 1] * nw[k0 + 1] * sc);
        g_qkvfrag[idx * 2 + 1] = packh2f(wr[k0 + 8] * nw[k0 + 8] * sc, wr[k0 + 9] * nw[k0 + 9] * sc);
    }
    if (idx < 1024) {  // proj weight fragments
        int lane = idx & 31, kt = (idx >> 5) & 3, ntile = idx >> 7;
        int n  = ntile * 8 + (lane >> 2);
        int k0 = kt * 16 + (lane & 3) * 2;
        const float* wr = pw + n * 64;
        g_projfrag[idx * 2 + 0] = packh2f(wr[k0],     wr[k0 + 1]);
        g_projfrag[idx * 2 + 1] = packh2f(wr[k0 + 8], wr[k0 + 9]);
    }
    if (idx < 96) {    // folded LN-bias through qkv (per output col pair), scale folded
        float b0 = 0.f, b1 = 0.f;
        int c = idx * 2;
        for (int k = 0; k < 64; k++) {
            b0 += nb[k] * qw[c * 64 + k];
            b1 += nb[k] * qw[(c + 1) * 64 + k];
        }
        float sc = (c < 64) ? 0.25f * LOG2E : 1.0f;
        g_qkvbh[idx] = packh2f(b0 * sc, b1 * sc);
    }
    if (idx < 4096) {  // rel-pos bias fragments (half2, *log2e), layout [warp][mt][j][lane][2]
        int lane = idx & 31, j = (idx >> 5) & 7, mt = (idx >> 8) & 1, warp = idx >> 9;
        int h  = warp >> 1;
        int m0 = (warp & 1) * 32;
        int g  = lane >> 2, tig = lane & 3;
        int rr = m0 + mt * 16 + g;
        int cc = j * 8 + tig * 2;
        auto bias = [&](int r, int c) {
            int dy = (r >> 3) - (c >> 3);
            int dx = (r & 7) - (c & 7);
            return rpb[((dy + 7) * 15 + (dx + 7)) * 4 + h] * LOG2E;
        };
        g_biasfh[idx * 2 + 0] = packh2f(bias(rr, cc),     bias(rr, cc + 1));
        g_biasfh[idx * 2 + 1] = packh2f(bias(rr + 8, cc), bias(rr + 8, cc + 1));
    }
}

__device__ __forceinline__ unsigned saddr(const void* p) {
    return (unsigned)__cvta_generic_to_shared(p);
}
__device__ __forceinline__ void ldsm_x4(unsigned a, unsigned& r0, unsigned& r1, unsigned& r2, unsigned& r3) {
    asm volatile("ldmatrix.sync.aligned.m8n8.x4.shared.b16 {%0,%1,%2,%3}, [%4];"
                 : "=r"(r0), "=r"(r1), "=r"(r2), "=r"(r3) : "r"(a));
}
__device__ __forceinline__ void ldsm_x4t(unsigned a, unsigned& r0, unsigned& r1, unsigned& r2, unsigned& r3) {
    asm volatile("ldmatrix.sync.aligned.m8n8.x4.trans.shared.b16 {%0,%1,%2,%3}, [%4];"
                 : "=r"(r0), "=r"(r1), "=r"(r2), "=r"(r3) : "r"(a));
}
__device__ __forceinline__ void mmah(uint2& c, unsigned a0, unsigned a1, unsigned a2, unsigned a3,
                                     unsigned b0, unsigned b1) {
    asm volatile("mma.sync.aligned.m16n8k16.row.col.f16.f16.f16.f16 "
                 "{%0,%1}, {%2,%3,%4,%5}, {%6,%7}, {%0,%1};"
                 : "+r"(c.x), "+r"(c.y)
                 : "r"(a0), "r"(a1), "r"(a2), "r"(a3), "r"(b0), "r"(b1));
}
__device__ __forceinline__ unsigned hadd2u(unsigned a, unsigned b) {
    __half2 r = __hadd2(*(__half2*)&a, *(__half2*)&b);
    return *(unsigned*)&r;
}
__device__ __forceinline__ unsigned hsub2u(unsigned a, unsigned b) {
    __half2 r = __hsub2(*(__half2*)&a, *(__half2*)&b);
    return *(unsigned*)&r;
}
__device__ __forceinline__ unsigned hmax2u(unsigned a, unsigned b) {
    __half2 r = __hmax2(*(__half2*)&a, *(__half2*)&b);
    return *(unsigned*)&r;
}
__device__ __forceinline__ unsigned hmul2u(unsigned a, unsigned b) {
    __half2 r = __hmul2(*(__half2*)&a, *(__half2*)&b);
    return *(unsigned*)&r;
}
__device__ __forceinline__ unsigned ex2h2(unsigned a) {
    unsigned r;
    asm("ex2.approx.f16x2 %0, %1;" : "=r"(r) : "r"(a));
    return r;
}
__device__ __forceinline__ unsigned hswap(unsigned a) {      // swap the two halves
    return __byte_perm(a, a, 0x1032);
}
__device__ __forceinline__ float2 h2f2(unsigned u) {
    return __half22float2(*(__half2*)&u);
}
__device__ __forceinline__ float hlo2f(unsigned u) {
    return __half2float(__low2half(*(__half2*)&u));
}

__global__ __launch_bounds__(256, 4)
void ewa_kernel(const float* __restrict__ x,
                const float* __restrict__ ascale,
                float* __restrict__ out) {
    extern __shared__ char smem[];
    __half* XN = (__half*)(smem + OFF_XN);   // [64][72]  Z / AO
    __half* KV = (__half*)(smem + OFF_KV);   // [64][136] K | V

    const int tid  = threadIdx.x;
    const int lane = tid & 31;
    const int warp = tid >> 5;
    const int g    = lane >> 2;
    const int tig  = lane & 3;
    const int l2   = lane & 15;

    const int win = blockIdx.x;
    const int b   = win >> 10;
    const int rem = win & 1023;
    const int wy  = rem >> 5;
    const int wx  = rem & 31;

    const int h  = warp >> 1;          // head (phases 2-3)
    const int m0 = (warp & 1) * 32;

    // ---- Phase 1: direct token-major load + in-register LayerNorm -> XN (fp16 Z) ----
    {
        int t = tid >> 2, q = tid & 3;            // token, channel quarter
        int pix = (wy * 8 + (t >> 3)) * 256 + wx * 8 + (t & 7);
        const float* base = x + (b * 64 + q * 16) * 65536 + pix;
        float v[16];
        #pragma unroll
        for (int i = 0; i < 16; i++) v[i] = base[i * 65536];
        float s = 0.f, ss = 0.f;
        #pragma unroll
        for (int i = 0; i < 16; i++) { s += v[i]; ss += v[i] * v[i]; }
        s  += __shfl_xor_sync(0xffffffffu, s, 1);  ss += __shfl_xor_sync(0xffffffffu, ss, 1);
        s  += __shfl_xor_sync(0xffffffffu, s, 2);  ss += __shfl_xor_sync(0xffffffffu, ss, 2);
        float mu   = s * (1.f / 64.f);
        float var  = ss * (1.f / 64.f) - mu * mu;
        float rstd = rsqrtf(var + 1e-5f);
        unsigned h8[8];
        #pragma unroll
        for (int i = 0; i < 8; i++)
            h8[i] = packh2f((v[2 * i] - mu) * rstd, (v[2 * i + 1] - mu) * rstd);
        uint4* dst = (uint4*)(XN + t * 72 + q * 16);
        dst[0] = make_uint4(h8[0], h8[1], h8[2], h8[3]);
        dst[1] = make_uint4(h8[4], h8[5], h8[6], h8[7]);
    }
    __syncthreads();

    // ---- Phase 2: QKV GEMM. Q for own (head, rows) stays in registers; K/V -> smem ----
    unsigned qa[2][4];   // Q as A-fragments for QK^T, per mt
    {
        uint2 qacc[2][2], kvacc[2][4];
        #pragma unroll
        for (int mt = 0; mt < 2; mt++) {
            qacc[mt][0] = make_uint2(0u, 0u); qacc[mt][1] = make_uint2(0u, 0u);
            #pragma unroll
            for (int j = 0; j < 4; j++) kvacc[mt][j] = make_uint2(0u, 0u);
        }
        #pragma unroll
        for (int kt = 0; kt < 4; kt++) {
            unsigned a[2][4];
            #pragma unroll
            for (int mt = 0; mt < 2; mt++)
                ldsm_x4(saddr(XN + (m0 + mt * 16 + l2) * 72 + kt * 16 + (lane >> 4) * 8),
                        a[mt][0], a[mt][1], a[mt][2], a[mt][3]);
            uint2 qb[2], kvb[4];
            #pragma unroll
            for (int j = 0; j < 2; j++)
                qb[j] = *(const uint2*)(g_qkvfrag + (((h * 2 + j) * 4 + kt) * 32 + lane) * 2);
            #pragma unroll
            for (int j = 0; j < 4; j++)
                kvb[j] = *(const uint2*)(g_qkvfrag + (((8 + h * 4 + j) * 4 + kt) * 32 + lane) * 2);
            #pragma unroll
            for (int mt = 0; mt < 2; mt++) {
                #pragma unroll
                for (int j = 0; j < 2; j++)
                    mmah(qacc[mt][j], a[mt][0], a[mt][1], a[mt][2], a[mt][3], qb[j].x, qb[j].y);
                #pragma unroll
                for (int j = 0; j < 4; j++)
                    mmah(kvacc[mt][j], a[mt][0], a[mt][1], a[mt][2], a[mt][3], kvb[j].x, kvb[j].y);
            }
        }
        // Q: D-frag (+bias) == A-frag for QK^T
        unsigned bq0 = g_qkvbh[h * 8 + tig];
        unsigned bq1 = g_qkvbh[h * 8 + 4 + tig];
        #pragma unroll
        for (int mt = 0; mt < 2; mt++) {
            qa[mt][0] = hadd2u(qacc[mt][0].x, bq0);
            qa[mt][1] = hadd2u(qacc[mt][0].y, bq0);
            qa[mt][2] = hadd2u(qacc[mt][1].x, bq1);
            qa[mt][3] = hadd2u(qacc[mt][1].y, bq1);
        }
        // K/V -> smem (smem col = global col - 64)
        #pragma unroll
        for (int j = 0; j < 4; j++) {
            int col = h * 32 + j * 8 + tig * 2;
            unsigned bh = g_qkvbh[32 + h * 16 + j * 4 + tig];
            #pragma unroll
            for (int mt = 0; mt < 2; mt++) {
                int row = m0 + mt * 16 + g;
                *(unsigned*)(KV + row * 136 + col)       = hadd2u(kvacc[mt][j].x, bh);
                *(unsigned*)(KV + (row + 8) * 136 + col) = hadd2u(kvacc[mt][j].y, bh);
            }
        }
    }
    __syncthreads();

    // ---- Phase 3: attention (log2-domain logits, half2 softmax, bias as C-init) ----
    {
        unsigned kb[8][2];
        #pragma unroll
        for (int jp = 0; jp < 4; jp++) {        // K fragments via ldmatrix.x4 (2 n-tiles each)
            unsigned r0, r1, r2, r3;
            int j  = (lane >> 4);               // n-tile within pair
            int kh = (lane >> 3) & 1;
            ldsm_x4(saddr(KV + ((jp * 2 + j) * 8 + (lane & 7)) * 136 + h * 16 + kh * 8),
                    r0, r1, r2, r3);
            kb[jp * 2 + 0][0] = r0; kb[jp * 2 + 0][1] = r1;
            kb[jp * 2 + 1][0] = r2; kb[jp * 2 + 1][1] = r3;
        }

        #pragma unroll
        for (int mt = 0; mt < 2; mt++) {
            const uint2* bfh = (const uint2*)(g_biasfh) + ((warp * 2 + mt) * 8) * 32 + lane;
            uint2 s[8];
            #pragma unroll
            for (int j = 0; j < 8; j++) {
                uint2 bv = bfh[j * 32];
                s[j].x = bv.x; s[j].y = bv.y;    // bias as accumulator init
                mmah(s[j], qa[mt][0], qa[mt][1], qa[mt][2], qa[mt][3], kb[j][0], kb[j][1]);
            }

            unsigned mh0 = packh2f(-65504.f, -65504.f), mh1 = mh0;
            #pragma unroll
            for (int j = 0; j < 8; j++) {
                mh0 = hmax2u(mh0, s[j].x);
                mh1 = hmax2u(mh1, s[j].y);
            }
            mh0 = hmax2u(mh0, __shfl_xor_sync(0xffffffffu, mh0, 1));
            mh0 = hmax2u(mh0, __shfl_xor_sync(0xffffffffu, mh0, 2));
            mh0 = hmax2u(mh0, hswap(mh0));            // row max in both halves
            mh1 = hmax2u(mh1, __shfl_xor_sync(0xffffffffu, mh1, 1));
            mh1 = hmax2u(mh1, __shfl_xor_sync(0xffffffffu, mh1, 2));
            mh1 = hmax2u(mh1, hswap(mh1));

            unsigned sum0 = 0u, sum1 = 0u;            // half2 zeros
            #pragma unroll
            for (int j = 0; j < 8; j++) {
                s[j].x = ex2h2(hsub2u(s[j].x, mh0));  // p = 2^(l - m)
                s[j].y = ex2h2(hsub2u(s[j].y, mh1));
                sum0 = hadd2u(sum0, s[j].x);
                sum1 = hadd2u(sum1, s[j].y);
            }
            sum0 = hadd2u(sum0, __shfl_xor_sync(0xffffffffu, sum0, 1));
            sum0 = hadd2u(sum0, __shfl_xor_sync(0xffffffffu, sum0, 2));
            sum0 = hadd2u(sum0, hswap(sum0));
            sum1 = hadd2u(sum1, __shfl_xor_sync(0xffffffffu, sum1, 1));
            sum1 = hadd2u(sum1, __shfl_xor_sync(0xffffffffu, sum1, 2));
            sum1 = hadd2u(sum1, hswap(sum1));

            // AV with unnormalized probs; V fragments via ldmatrix.x4.trans
            uint2 o[2];
            o[0].x = o[0].y = o[1].x = o[1].y = 0u;
            #pragma unroll
            for (int kt = 0; kt < 4; kt++) {
                unsigned v0, v1, v2, v3;
                ldsm_x4t(saddr(KV + (kt * 16 + (lane & 7) + ((lane >> 3) & 1) * 8) * 136
                               + 64 + h * 16 + (lane >> 4) * 8),
                         v0, v1, v2, v3);
                mmah(o[0], s[2 * kt].x, s[2 * kt].y, s[2 * kt + 1].x, s[2 * kt + 1].y, v0, v1);
                mmah(o[1], s[2 * kt].x, s[2 * kt].y, s[2 * kt + 1].x, s[2 * kt + 1].y, v2, v3);
            }
            float f0 = 1.f / hlo2f(sum0);
            float f1 = 1.f / hlo2f(sum1);
            unsigned i0 = packh2f(f0, f0);
            unsigned i1 = packh2f(f1, f1);
            #pragma unroll
            for (int nt = 0; nt < 2; nt++) {
                int row = m0 + mt * 16 + g;
                int col = h * 16 + nt * 8 + tig * 2;
                *(unsigned*)(XN + row * 72 + col)       = hmul2u(o[nt].x, i0);
                *(unsigned*)(XN + (row + 8) * 72 + col) = hmul2u(o[nt].y, i1);
            }
        }
    }
    __syncthreads();

    // ---- Phase 4: proj GEMM [64,64]x[64,64] + residual + write out (fp16 acc) ----
    {
        const int ntb = (warp >> 1) * 2;      // ntile base (8-col tiles)
        uint2 acc[2][2];
        acc[0][0] = make_uint2(0u, 0u); acc[0][1] = make_uint2(0u, 0u);
        acc[1][0] = make_uint2(0u, 0u); acc[1][1] = make_uint2(0u, 0u);
        #pragma unroll
        for (int kt = 0; kt < 4; kt++) {
            unsigned a[2][4];
            #pragma unroll
            for (int mt = 0; mt < 2; mt++)
                ldsm_x4(saddr(XN + (m0 + mt * 16 + l2) * 72 + kt * 16 + (lane >> 4) * 8),
                        a[mt][0], a[mt][1], a[mt][2], a[mt][3]);
            uint2 bf[2];
            #pragma unroll
            for (int nt = 0; nt < 2; nt++)
                bf[nt] = *(const uint2*)(g_projfrag + (((ntb + nt) * 4 + kt) * 32 + lane) * 2);
            #pragma unroll
            for (int mt = 0; mt < 2; mt++)
                #pragma unroll
                for (int nt = 0; nt < 2; nt++)
                    mmah(acc[mt][nt], a[mt][0], a[mt][1], a[mt][2], a[mt][3], bf[nt].x, bf[nt].y);
        }
        float ssc = ascale[0];
        #pragma unroll
        for (int mt = 0; mt < 2; mt++)
            #pragma unroll
            for (int nt = 0; nt < 2; nt++) {
                int ch = (ntb + nt) * 8 + tig * 2;
                float2 lo = h2f2(acc[mt][nt].x);   // rows m0+mt*16+g
                float2 hi = h2f2(acc[mt][nt].y);   // rows +8
                #pragma unroll
                for (int hf = 0; hf < 2; hf++) {
                    int row = m0 + mt * 16 + g + hf * 8;
                    float2 v = hf ? hi : lo;
                    int gi0 = ((b * 64 + ch) * 256 + wy * 8 + (row >> 3)) * 256 + wx * 8 + (row & 7);
                    int gi1 = gi0 + 65536;   // ch+1
                    out[gi0] = x[gi0] + ssc * v.x;
                    out[gi1] = x[gi1] + ssc * v.y;
                }
            }
    }
}

extern "C" void kernel_launch(void* const* d_in, const int* in_sizes, int n_in,
                              void* d_out, int out_size) {
    const float* x  = (const float*)d_in[0];
    const float* nw = (const float*)d_in[1];
    const float* nb = (const float*)d_in[2];
    const float* qw = (const float*)d_in[3];
    const float* pw = (const float*)d_in[4];
    const float* sc = (const float*)d_in[5];
    const float* rp = (const float*)d_in[6];
    float* out = (float*)d_out;

    cudaFuncSetAttribute(ewa_kernel, cudaFuncAttributeMaxDynamicSharedMemorySize, SMEM_BYTES);

    prep_kernel<<<32, 256>>>(qw, pw, nw, nb, rp);
    ewa_kernel<<<NWIN, TPB, SMEM_BYTES>>>(x, sc, out);
}